// round 4
// baseline (speedup 1.0000x reference)
#include <cuda_runtime.h>
#include <math.h>
#include <stdint.h>

// Problem dims (fixed by the dataset)
#define HD   512          // H
#define PD   256          // P (complex modes) -> 512 interleaved reals
#define LD   4096         // L
#define BSZ  8
#define MROWS (BSZ*LD)    // 32768
#define CH   64           // scan chunk length
#define NCH  (LD/CH)      // 64 chunks

// ---------------- scratch (device globals: no allocation allowed) ----------
__device__ __align__(16) float  g_Bu[(size_t)MROWS*HD];   // 64 MB, interleaved complex (re,im)
__device__ __align__(16) float  g_W1[HD*HD];              // 1 MB
__device__ __align__(16) float  g_W2[HD*HD];              // 1 MB
__device__ float2 g_lambda[PD];
__device__ float2 g_lamS[PD];
__device__ float2 g_coef[PD];
__device__ float2 g_bout [BSZ*NCH*PD];
__device__ float2 g_carry[BSZ*NCH*PD];

// ---------------- packed f32x2 helpers -------------------------------------
__device__ __forceinline__ unsigned long long pack_dup(float a) {
    unsigned int u = __float_as_uint(a);
    unsigned long long r;
    asm("mov.b64 %0, {%1, %1};" : "=l"(r) : "r"(u));
    return r;
}
__device__ __forceinline__ void fma2(unsigned long long &d,
                                     unsigned long long a, unsigned long long b) {
    asm("fma.rn.f32x2 %0, %1, %2, %0;" : "+l"(d) : "l"(a), "l"(b));
}
__device__ __forceinline__ float2 unpack2(unsigned long long v) {
    unsigned int lo, hi;
    asm("mov.b64 {%0, %1}, %2;" : "=r"(lo), "=r"(hi) : "l"(v));
    return make_float2(__uint_as_float(lo), __uint_as_float(hi));
}

// ---------------- prep: discretization + weight assembly --------------------
__global__ void prep1_kernel(const float* __restrict__ Lre,
                             const float* __restrict__ Lim,
                             const float* __restrict__ logstep) {
    int p = threadIdx.x;
    if (p >= PD) return;
    double lre = (double)Lre[p], lim = (double)Lim[p];
    double st  = exp((double)logstep[p]);
    double ar = lre * st, ai = lim * st;
    double er = exp(ar);
    double lr = er * cos(ai), li = er * sin(ai);          // lambda_bar
    g_lambda[p] = make_float2((float)lr, (float)li);
    double eS = exp(ar * (double)CH);                     // lambda_bar^CH
    g_lamS[p]  = make_float2((float)(eS * cos(ai * (double)CH)),
                             (float)(eS * sin(ai * (double)CH)));
    // coef = (lambda_bar - 1) / Lam  (complex divide)
    double nr = lr - 1.0, ni = li;
    double d2 = lre * lre + lim * lim;
    g_coef[p] = make_float2((float)((nr * lre + ni * lim) / d2),
                            (float)((ni * lre - nr * lim) / d2));
}

__global__ void prep2_kernel(const float* __restrict__ B,
                             const float* __restrict__ C) {
    int tot = HD * HD;
    for (int idx = blockIdx.x * blockDim.x + threadIdx.x;
         idx < 2 * tot; idx += gridDim.x * blockDim.x) {
        if (idx < tot) {
            // W1[h][n] : n=2p -> Re(B_bar[p][h]), n=2p+1 -> Im(B_bar[p][h])
            int h = idx >> 9, n = idx & 511;
            int p = n >> 1;
            float2 c = g_coef[p];
            float b0 = B[((size_t)p * HD + h) * 2 + 0];
            float b1 = B[((size_t)p * HD + h) * 2 + 1];
            g_W1[idx] = (n & 1) ? fmaf(c.x, b1,  c.y * b0)
                                : fmaf(c.x, b0, -c.y * b1);
        } else {
            // W2[k][h] : k=2p -> 2*Cre[h][p], k=2p+1 -> -2*Cim[h][p]
            int j = idx - tot;
            int k = j >> 9, h = j & 511;
            int p = k >> 1;
            float cv = C[((size_t)h * PD + p) * 2 + (k & 1)];
            g_W2[j] = (k & 1) ? (-2.0f * cv) : (2.0f * cv);
        }
    }
}

// ---------------- 3-pass chunked complex scan over L -------------------------
// pass 1: per-(b,chunk,p) local inclusive scan in place; emit chunk-final state
__global__ void scan1_kernel() {
    int tid = blockIdx.x * 256 + threadIdx.x;    // 131072 threads
    int p = tid & (PD - 1);
    int c = (tid >> 8) & (NCH - 1);
    int b = tid >> 14;
    float2 lam = g_lambda[p];
    float xr = 0.f, xi = 0.f;
    float2* base = (float2*)g_Bu + ((size_t)(b * LD + c * CH)) * PD + p;
    #pragma unroll 8
    for (int j = 0; j < CH; j++) {
        float2 v = base[(size_t)j * PD];
        float nr = fmaf(lam.x, xr, fmaf(-lam.y, xi, v.x));
        float ni = fmaf(lam.y, xr, fmaf( lam.x, xi, v.y));
        xr = nr; xi = ni;
        base[(size_t)j * PD] = make_float2(xr, xi);
    }
    g_bout[(b * NCH + c) * PD + p] = make_float2(xr, xi);
}

// pass 2: per-(b,p) scan over chunk carries
__global__ void scan2_kernel() {
    int b = blockIdx.x;
    int p = threadIdx.x;
    float2 lS = g_lamS[p];
    float cr = 0.f, ci = 0.f;
    for (int c = 0; c < NCH; c++) {
        int idx = (b * NCH + c) * PD + p;
        g_carry[idx] = make_float2(cr, ci);
        float2 bo = g_bout[idx];
        float nr = fmaf(lS.x, cr, fmaf(-lS.y, ci, bo.x));
        float ni = fmaf(lS.y, cr, fmaf( lS.x, ci, bo.y));
        cr = nr; ci = ni;
    }
}

// pass 3: fixup: xs[l] = local[l] + lambda^{j+1} * carry_in
__global__ void scan3_kernel() {
    int tid = blockIdx.x * 256 + threadIdx.x;
    int p = tid & (PD - 1);
    int c = (tid >> 8) & (NCH - 1);
    int b = tid >> 14;
    if (c == 0) return;                          // carry is zero
    float2 car = g_carry[(b * NCH + c) * PD + p];
    float2 lam = g_lambda[p];
    float tr = lam.x * car.x - lam.y * car.y;    // lambda^1 * carry
    float ti = lam.x * car.y + lam.y * car.x;
    float2* base = (float2*)g_Bu + ((size_t)(b * LD + c * CH)) * PD + p;
    #pragma unroll 8
    for (int j = 0; j < CH; j++) {
        float2 v = base[(size_t)j * PD];
        v.x += tr; v.y += ti;
        base[(size_t)j * PD] = v;
        float nr = lam.x * tr - lam.y * ti;
        float ni = lam.x * ti + lam.y * tr;
        tr = nr; ti = ni;
    }
}

// ---------------- SGEMM (f32x2 packed), 128x128 tile, BK=16, 8x8/thread ------
// MODE 0: Cout(g_Bu) = Aext(x) @ g_W1
// MODE 1: Cout(ext)  = g_Bu @ g_W2  + D*x epilogue
template <int MODE>
__global__ __launch_bounds__(256, 2)
void sgemm_kernel(const float* __restrict__ Aext,
                  float* __restrict__ Cext,
                  const float* __restrict__ skipX,
                  const float* __restrict__ Dv) {
    __shared__ float As[16][128];   // transposed: As[k][m]
    __shared__ float Bs[16][128];   // Bs[k][n]

    const float* A = (MODE == 0) ? Aext : g_Bu;
    const float* W = (MODE == 0) ? g_W1 : g_W2;
    float*       Co = (MODE == 0) ? g_Bu : Cext;

    int tid = threadIdx.x;
    int tx = tid & 15;            // n-direction (8 cols each)
    int ty = tid >> 4;            // m-direction (8 rows each)
    int row0 = blockIdx.y * 128;
    int col0 = blockIdx.x * 128;

    // loader indices
    int ar = tid >> 2;            // 0..63
    int ac = (tid & 3) * 4;       // 0,4,8,12
    int wr = tid >> 5;            // 0..7
    int wc = (tid & 31) * 4;      // 0..124

    unsigned long long acc[8][4];
    #pragma unroll
    for (int i = 0; i < 8; i++)
        #pragma unroll
        for (int j = 0; j < 4; j++) acc[i][j] = 0ull;

    for (int kt = 0; kt < 512; kt += 16) {
        float4 a0 = *(const float4*)&A[(size_t)(row0 + ar     ) * 512 + kt + ac];
        float4 a1 = *(const float4*)&A[(size_t)(row0 + ar + 64) * 512 + kt + ac];
        float4 w0 = *(const float4*)&W[(size_t)(kt + wr    ) * 512 + col0 + wc];
        float4 w1 = *(const float4*)&W[(size_t)(kt + wr + 8) * 512 + col0 + wc];

        __syncthreads();   // previous tile consumed
        As[ac + 0][ar] = a0.x; As[ac + 1][ar] = a0.y;
        As[ac + 2][ar] = a0.z; As[ac + 3][ar] = a0.w;
        As[ac + 0][ar + 64] = a1.x; As[ac + 1][ar + 64] = a1.y;
        As[ac + 2][ar + 64] = a1.z; As[ac + 3][ar + 64] = a1.w;
        *(float4*)&Bs[wr    ][wc] = w0;
        *(float4*)&Bs[wr + 8][wc] = w1;
        __syncthreads();

        #pragma unroll
        for (int k = 0; k < 16; k++) {
            float4 af0 = *(const float4*)&As[k][ty * 8];
            float4 af1 = *(const float4*)&As[k][ty * 8 + 4];
            ulonglong2 b01 = *(const ulonglong2*)&Bs[k][tx * 8];
            ulonglong2 b23 = *(const ulonglong2*)&Bs[k][tx * 8 + 4];
            unsigned long long bb0 = b01.x, bb1 = b01.y, bb2 = b23.x, bb3 = b23.y;
            float av[8] = {af0.x, af0.y, af0.z, af0.w, af1.x, af1.y, af1.z, af1.w};
            #pragma unroll
            for (int i = 0; i < 8; i++) {
                unsigned long long ad = pack_dup(av[i]);
                fma2(acc[i][0], ad, bb0);
                fma2(acc[i][1], ad, bb1);
                fma2(acc[i][2], ad, bb2);
                fma2(acc[i][3], ad, bb3);
            }
        }
    }

    // epilogue
    int n0 = col0 + tx * 8;
    float dv[8];
    if (MODE == 1) {
        #pragma unroll
        for (int j = 0; j < 8; j++) dv[j] = Dv[n0 + j];
    }
    #pragma unroll
    for (int i = 0; i < 8; i++) {
        int m = row0 + ty * 8 + i;
        float out[8];
        #pragma unroll
        for (int j = 0; j < 4; j++) {
            float2 v = unpack2(acc[i][j]);
            out[2 * j] = v.x; out[2 * j + 1] = v.y;
        }
        if (MODE == 1) {
            const float* xr = &skipX[(size_t)m * 512 + n0];
            float4 x0 = *(const float4*)&xr[0];
            float4 x1 = *(const float4*)&xr[4];
            out[0] = fmaf(dv[0], x0.x, out[0]);
            out[1] = fmaf(dv[1], x0.y, out[1]);
            out[2] = fmaf(dv[2], x0.z, out[2]);
            out[3] = fmaf(dv[3], x0.w, out[3]);
            out[4] = fmaf(dv[4], x1.x, out[4]);
            out[5] = fmaf(dv[5], x1.y, out[5]);
            out[6] = fmaf(dv[6], x1.z, out[6]);
            out[7] = fmaf(dv[7], x1.w, out[7]);
        }
        *(float4*)&Co[(size_t)m * 512 + n0    ] = make_float4(out[0], out[1], out[2], out[3]);
        *(float4*)&Co[(size_t)m * 512 + n0 + 4] = make_float4(out[4], out[5], out[6], out[7]);
    }
}

// ---------------- launch -----------------------------------------------------
extern "C" void kernel_launch(void* const* d_in, const int* in_sizes, int n_in,
                              void* d_out, int out_size) {
    const float* x       = (const float*)d_in[0];   // (8,4096,512)
    const float* Lre     = (const float*)d_in[1];   // (256)
    const float* Lim     = (const float*)d_in[2];   // (256)
    const float* B       = (const float*)d_in[3];   // (256,512,2)
    const float* C       = (const float*)d_in[4];   // (512,256,2)
    const float* D       = (const float*)d_in[5];   // (512)
    const float* logstep = (const float*)d_in[6];   // (256)
    float* out = (float*)d_out;                     // (8,4096,512) fp32

    prep1_kernel<<<1, 256>>>(Lre, Lim, logstep);
    prep2_kernel<<<256, 256>>>(B, C);

    dim3 gemm_grid(HD / 128, MROWS / 128);          // (4, 256)
    sgemm_kernel<0><<<gemm_grid, 256>>>(x, nullptr, nullptr, nullptr);

    scan1_kernel<<<(BSZ * NCH * PD) / 256, 256>>>();  // 512 blocks
    scan2_kernel<<<BSZ, PD>>>();
    scan3_kernel<<<(BSZ * NCH * PD) / 256, 256>>>();

    sgemm_kernel<1><<<gemm_grid, 256>>>(nullptr, out, x, D);
}

// round 6
// speedup vs baseline: 1.1892x; 1.1892x over previous
#include <cuda_runtime.h>
#include <cuda_bf16.h>
#include <math.h>
#include <stdint.h>

#define HD 512
#define PD 256
#define LD 4096
#define BSZ 8
#define MROWS (BSZ*LD)      // 32768
#define CH 64
#define NCH (LD/CH)         // 64

// ---- device scratch (no allocation allowed) ----
__device__ __align__(16) float g_Bu[(size_t)MROWS*HD];        // 64 MB fp32
__device__ __align__(16) float g_W1[HD*HD];                   // [k][n]
__device__ __align__(16) float g_W2[HD*HD];                   // [k][n]
__device__ __align__(16) __nv_bfloat16 g_Ah[(size_t)MROWS*HD];  // 32 MB [m][k]
__device__ __align__(16) __nv_bfloat16 g_Al[(size_t)MROWS*HD];  // 32 MB
__device__ __align__(16) __nv_bfloat16 g_W1h[HD*HD];          // [n][k]
__device__ __align__(16) __nv_bfloat16 g_W1l[HD*HD];
__device__ __align__(16) __nv_bfloat16 g_W2h[HD*HD];
__device__ __align__(16) __nv_bfloat16 g_W2l[HD*HD];
__device__ float2 g_lambda[PD];
__device__ float2 g_lamS[PD];
__device__ float2 g_coef[PD];
__device__ float2 g_bout [BSZ*NCH*PD];
__device__ float2 g_carry[BSZ*NCH*PD];

// ---- PTX helpers ----
__device__ __forceinline__ uint32_t s2u(const void* p) {
    uint32_t a;
    asm("{ .reg .u64 t; cvta.to.shared.u64 t, %1; cvt.u32.u64 %0, t; }" : "=r"(a) : "l"(p));
    return a;
}
__device__ __forceinline__ void cp16(uint32_t dst, const void* src) {
    asm volatile("cp.async.cg.shared.global [%0], [%1], 16;" :: "r"(dst), "l"(src) : "memory");
}
__device__ __forceinline__ void ldm_x4(uint32_t* r, uint32_t addr) {
    asm volatile("ldmatrix.sync.aligned.m8n8.x4.shared.b16 {%0,%1,%2,%3}, [%4];"
                 : "=r"(r[0]), "=r"(r[1]), "=r"(r[2]), "=r"(r[3]) : "r"(addr));
}
__device__ __forceinline__ void mma16816(float* d, const uint32_t* a, uint32_t b0, uint32_t b1) {
    asm volatile("mma.sync.aligned.m16n8k16.row.col.f32.bf16.bf16.f32 "
                 "{%0,%1,%2,%3}, {%4,%5,%6,%7}, {%8,%9}, {%0,%1,%2,%3};"
                 : "+f"(d[0]), "+f"(d[1]), "+f"(d[2]), "+f"(d[3])
                 : "r"(a[0]), "r"(a[1]), "r"(a[2]), "r"(a[3]), "r"(b0), "r"(b1));
}

// ---- prep: discretization + weight assembly ----
__global__ void prep1_kernel(const float* __restrict__ Lre,
                             const float* __restrict__ Lim,
                             const float* __restrict__ logstep) {
    int p = threadIdx.x;
    if (p >= PD) return;
    double lre = (double)Lre[p], lim = (double)Lim[p];
    double st  = exp((double)logstep[p]);
    double ar = lre * st, ai = lim * st;
    double er = exp(ar);
    double lr = er * cos(ai), li = er * sin(ai);
    g_lambda[p] = make_float2((float)lr, (float)li);
    double eS = exp(ar * (double)CH);
    g_lamS[p]  = make_float2((float)(eS * cos(ai * (double)CH)),
                             (float)(eS * sin(ai * (double)CH)));
    double nr = lr - 1.0, ni = li;
    double d2 = lre * lre + lim * lim;
    g_coef[p] = make_float2((float)((nr * lre + ni * lim) / d2),
                            (float)((ni * lre - nr * lim) / d2));
}

__global__ void prep2_kernel(const float* __restrict__ B,
                             const float* __restrict__ C) {
    int tot = HD * HD;
    for (int idx = blockIdx.x * blockDim.x + threadIdx.x;
         idx < 2 * tot; idx += gridDim.x * blockDim.x) {
        if (idx < tot) {
            int h = idx >> 9, n = idx & 511;     // W1[k=h][n]
            int p = n >> 1;
            float2 c = g_coef[p];
            float b0 = B[((size_t)p * HD + h) * 2 + 0];
            float b1 = B[((size_t)p * HD + h) * 2 + 1];
            g_W1[idx] = (n & 1) ? fmaf(c.x, b1,  c.y * b0)
                                : fmaf(c.x, b0, -c.y * b1);
        } else {
            int j = idx - tot;
            int k = j >> 9, h = j & 511;         // W2[k][n=h]
            int p = k >> 1;
            float cv = C[((size_t)h * PD + p) * 2 + (k & 1)];
            g_W2[j] = (k & 1) ? (-2.0f * cv) : (2.0f * cv);
        }
    }
}

// W[k][n] fp32 -> transposed bf16 hi/lo [n][k]
__global__ void packw_kernel() {
    for (int idx = blockIdx.x * blockDim.x + threadIdx.x;
         idx < 2 * HD * HD; idx += gridDim.x * blockDim.x) {
        int which = idx >> 18;
        int j = idx & (HD * HD - 1);
        int n = j >> 9, k = j & 511;
        float v = which ? g_W2[k * 512 + n] : g_W1[k * 512 + n];
        __nv_bfloat16 h = __float2bfloat16(v);
        __nv_bfloat16 l = __float2bfloat16(v - __bfloat162float(h));
        (which ? g_W2h : g_W1h)[n * 512 + k] = h;
        (which ? g_W2l : g_W1l)[n * 512 + k] = l;
    }
}

// x fp32 -> Ah/Al bf16 row-major
__global__ void convx_kernel(const float* __restrict__ x) {
    size_t nseg = (size_t)MROWS * 64;
    for (size_t g = (size_t)blockIdx.x * blockDim.x + threadIdx.x;
         g < nseg; g += (size_t)gridDim.x * blockDim.x) {
        size_t m = g >> 6; int k8 = (int)(g & 63);
        const float4* s4 = (const float4*)(x + m * 512 + k8 * 8);
        float4 a = s4[0], b = s4[1];
        float v[8] = {a.x, a.y, a.z, a.w, b.x, b.y, b.z, b.w};
        uint32_t hi[4], lo[4];
        #pragma unroll
        for (int i = 0; i < 4; i++) {
            __nv_bfloat16 ha = __float2bfloat16(v[2*i]), hb = __float2bfloat16(v[2*i+1]);
            float ra = v[2*i]   - __bfloat162float(ha);
            float rb = v[2*i+1] - __bfloat162float(hb);
            __nv_bfloat162 H = __halves2bfloat162(ha, hb);
            __nv_bfloat162 L = __floats2bfloat162_rn(ra, rb);
            hi[i] = *(uint32_t*)&H; lo[i] = *(uint32_t*)&L;
        }
        size_t off = m * 512 + k8 * 8;
        *(uint4*)(g_Ah + off) = make_uint4(hi[0], hi[1], hi[2], hi[3]);
        *(uint4*)(g_Al + off) = make_uint4(lo[0], lo[1], lo[2], lo[3]);
    }
}

// ---- 3-pass chunked complex scan ----
__global__ void scan1_kernel() {
    int tid = blockIdx.x * 256 + threadIdx.x;
    int p = tid & (PD - 1);
    int c = (tid >> 8) & (NCH - 1);
    int b = tid >> 14;
    float2 lam = g_lambda[p];
    float xr = 0.f, xi = 0.f;
    float2* base = (float2*)g_Bu + ((size_t)(b * LD + c * CH)) * PD + p;
    #pragma unroll 8
    for (int j = 0; j < CH; j++) {
        float2 v = base[(size_t)j * PD];
        float nr = fmaf(lam.x, xr, fmaf(-lam.y, xi, v.x));
        float ni = fmaf(lam.y, xr, fmaf( lam.x, xi, v.y));
        xr = nr; xi = ni;
        base[(size_t)j * PD] = make_float2(xr, xi);
    }
    g_bout[(b * NCH + c) * PD + p] = make_float2(xr, xi);
}

__global__ void scan2_kernel() {
    int b = blockIdx.x;
    int p = threadIdx.x;
    float2 lS = g_lamS[p];
    float cr = 0.f, ci = 0.f;
    for (int c = 0; c < NCH; c++) {
        int idx = (b * NCH + c) * PD + p;
        g_carry[idx] = make_float2(cr, ci);
        float2 bo = g_bout[idx];
        float nr = fmaf(lS.x, cr, fmaf(-lS.y, ci, bo.x));
        float ni = fmaf(lS.y, cr, fmaf( lS.x, ci, bo.y));
        cr = nr; ci = ni;
    }
}

// fused carry fixup + bf16 split-convert of xs -> Ah/Al row-major
__global__ void convxs_kernel() {
    int tid = blockIdx.x * 256 + threadIdx.x;
    int p = tid & (PD - 1);
    int c = (tid >> 8) & (NCH - 1);
    int b = tid >> 14;
    float2 lam = g_lambda[p];
    float tr = 0.f, ti = 0.f;
    if (c > 0) {
        float2 car = g_carry[(b * NCH + c) * PD + p];
        tr = lam.x * car.x - lam.y * car.y;
        ti = lam.x * car.y + lam.y * car.x;
    }
    const float2* src = (const float2*)g_Bu + ((size_t)(b * LD + c * CH)) * PD + p;
    size_t m0 = (size_t)b * LD + c * CH;
    #pragma unroll 4
    for (int j = 0; j < CH; j++) {
        float2 v = src[(size_t)j * PD];
        float re = v.x + tr, im = v.y + ti;
        float nr = lam.x * tr - lam.y * ti;
        float ni = lam.x * ti + lam.y * tr;
        tr = nr; ti = ni;
        size_t off = (m0 + j) * 512 + 2 * p;
        __nv_bfloat16 hr = __float2bfloat16(re), hm = __float2bfloat16(im);
        float rr = re - __bfloat162float(hr), ri = im - __bfloat162float(hm);
        __nv_bfloat162 H = __halves2bfloat162(hr, hm);
        __nv_bfloat162 L = __floats2bfloat162_rn(rr, ri);
        *(uint32_t*)(g_Ah + off) = *(uint32_t*)&H;
        *(uint32_t*)(g_Al + off) = *(uint32_t*)&L;
    }
}

// ---- HMMA bf16 split GEMM: C[128,128] per CTA, K = 3 terms x 512 ----
// MODE 0: g_Bu = x(Ah/Al) @ W1(h/l) ; MODE 1: out = xs(Ah/Al) @ W2(h/l) + D*x
#define NSTG 4
#define STGB 16384            // A 8KB + B 8KB per stage
#define GSMEM (NSTG*STGB)     // 64 KB

template <int MODE>
__global__ void __launch_bounds__(256, 2)
gemm_kernel(const float* __restrict__ skipX,
            float* __restrict__ Cext,
            const float* __restrict__ Dv) {
    extern __shared__ __align__(1024) unsigned char smem[];
    uint32_t sa = s2u(smem);
    int tid = threadIdx.x, wid = tid >> 5, lane = tid & 31;
    int row0 = blockIdx.y * 128, col0 = blockIdx.x * 128;
    float* Co = MODE ? Cext : g_Bu;
    const __nv_bfloat16* Wh = MODE ? g_W2h : g_W1h;
    const __nv_bfloat16* Wl = MODE ? g_W2l : g_W1l;

    int lr = tid >> 2, lc = tid & 3;       // loader: row 0..63(x2), 16B chunk 0..3

    auto load_stage = [&](int st, int it) {
        int seg = it >> 4, kt = it & 15;
        const __nv_bfloat16* As = (seg == 1) ? g_Al : g_Ah;
        const __nv_bfloat16* Bs = (seg == 2) ? Wl : Wh;
        int k0 = kt * 32 + lc * 8;
        uint32_t sA = sa + st * STGB;
        uint32_t sB = sA + 8192;
        #pragma unroll
        for (int i = 0; i < 2; i++) {
            int r = lr + i * 64;
            cp16(sA + (uint32_t)(lc * 128 + r) * 16, As + (size_t)(row0 + r) * 512 + k0);
            cp16(sB + (uint32_t)(lc * 128 + r) * 16, Bs + (size_t)(col0 + r) * 512 + k0);
        }
        asm volatile("cp.async.commit_group;" ::: "memory");
    };

    float acc[2][8][4];
    #pragma unroll
    for (int i = 0; i < 2; i++)
        #pragma unroll
        for (int j = 0; j < 8; j++)
            #pragma unroll
            for (int q = 0; q < 4; q++) acc[i][j][q] = 0.f;

    load_stage(0, 0);
    load_stage(1, 1);
    load_stage(2, 2);

    int wm = (wid & 3) * 32, wn = (wid >> 2) * 64;
    int lrow = lane & 15, lhalf = lane >> 4;

    #pragma unroll 1
    for (int it = 0; it < 48; it++) {
        int st = it & 3;
        asm volatile("cp.async.wait_group 2;" ::: "memory");
        __syncthreads();
        if (it + 3 < 48) load_stage((it + 3) & 3, it + 3);
        else asm volatile("cp.async.commit_group;" ::: "memory");

        uint32_t sA = sa + st * STGB, sB = sA + 8192;
        #pragma unroll
        for (int s = 0; s < 2; s++) {
            int ch = s * 2 + lhalf;
            uint32_t a[2][4], b[4][4];
            #pragma unroll
            for (int tm = 0; tm < 2; tm++)
                ldm_x4(a[tm], sA + (uint32_t)(ch * 128 + wm + tm * 16 + lrow) * 16);
            #pragma unroll
            for (int tp = 0; tp < 4; tp++)
                ldm_x4(b[tp], sB + (uint32_t)(ch * 128 + wn + tp * 16 + lrow) * 16);
            #pragma unroll
            for (int tm = 0; tm < 2; tm++)
                #pragma unroll
                for (int tn = 0; tn < 8; tn++) {
                    int tp = tn >> 1, w = tn & 1;
                    mma16816(acc[tm][tn], a[tm], b[tp][w], b[tp][w + 2]);
                }
        }
    }

    // epilogue: d-frag lane mapping: rows l>>2 (+8), cols (l&3)*2 (+1)
    int rbase = row0 + wm + (lane >> 2);
    int nb0 = col0 + wn + (lane & 3) * 2;
    #pragma unroll
    for (int tm = 0; tm < 2; tm++) {
        #pragma unroll
        for (int tn = 0; tn < 8; tn++) {
            int r = rbase + tm * 16;
            int n = nb0 + tn * 8;
            float2 v0 = make_float2(acc[tm][tn][0], acc[tm][tn][1]);
            float2 v1 = make_float2(acc[tm][tn][2], acc[tm][tn][3]);
            if (MODE == 1) {
                float d0 = Dv[n], d1 = Dv[n + 1];
                float2 x0 = *(const float2*)&skipX[(size_t)r * 512 + n];
                float2 x1 = *(const float2*)&skipX[(size_t)(r + 8) * 512 + n];
                v0.x = fmaf(d0, x0.x, v0.x); v0.y = fmaf(d1, x0.y, v0.y);
                v1.x = fmaf(d0, x1.x, v1.x); v1.y = fmaf(d1, x1.y, v1.y);
            }
            *(float2*)&Co[(size_t)r * 512 + n]       = v0;
            *(float2*)&Co[(size_t)(r + 8) * 512 + n] = v1;
        }
    }
}

// ---- launch ----
extern "C" void kernel_launch(void* const* d_in, const int* in_sizes, int n_in,
                              void* d_out, int out_size) {
    const float* x       = (const float*)d_in[0];
    const float* Lre     = (const float*)d_in[1];
    const float* Lim     = (const float*)d_in[2];
    const float* B       = (const float*)d_in[3];
    const float* C       = (const float*)d_in[4];
    const float* D       = (const float*)d_in[5];
    const float* logstep = (const float*)d_in[6];
    float* out = (float*)d_out;

    static int attr_done = 0;
    if (!attr_done) {
        cudaFuncSetAttribute(gemm_kernel<0>, cudaFuncAttributeMaxDynamicSharedMemorySize, GSMEM);
        cudaFuncSetAttribute(gemm_kernel<1>, cudaFuncAttributeMaxDynamicSharedMemorySize, GSMEM);
        attr_done = 1;
    }

    prep1_kernel<<<1, 256>>>(Lre, Lim, logstep);
    prep2_kernel<<<256, 256>>>(B, C);
    packw_kernel<<<512, 256>>>();
    convx_kernel<<<2048, 256>>>(x);

    dim3 gg(4, 256);   // (N/128, M/128)
    gemm_kernel<0><<<gg, 256, GSMEM>>>(nullptr, nullptr, nullptr);

    scan1_kernel<<<(BSZ * NCH * PD) / 256, 256>>>();
    scan2_kernel<<<BSZ, PD>>>();
    convxs_kernel<<<(BSZ * NCH * PD) / 256, 256>>>();

    gemm_kernel<1><<<gg, 256, GSMEM>>>(x, out, D);
}

// round 7
// speedup vs baseline: 1.6261x; 1.3674x over previous
#include <cuda_runtime.h>
#include <cuda_fp16.h>
#include <math.h>
#include <stdint.h>

#define HD 512
#define PD 256
#define LD 4096
#define BSZ 8
#define MROWS (BSZ*LD)      // 32768
#define CH 64
#define NCH (LD/CH)         // 64

// ---- device scratch (no allocation allowed) ----
__device__ __align__(16) float g_Bu[(size_t)MROWS*HD];        // 64 MB fp32
__device__ __align__(16) float g_W1[HD*HD];                   // [k][n]
__device__ __align__(16) float g_W2[HD*HD];                   // [k][n]
__device__ __align__(16) __half g_Ah[(size_t)MROWS*HD];       // 32 MB [m][k]
__device__ __align__(16) __half g_Al[(size_t)MROWS*HD];       // 32 MB
__device__ __align__(16) __half g_W1h[HD*HD];                 // [n][k]
__device__ __align__(16) __half g_W2h[HD*HD];
__device__ float2 g_lambda[PD];
__device__ float2 g_lamS[PD];
__device__ float2 g_coef[PD];
__device__ float2 g_bout [BSZ*NCH*PD];
__device__ float2 g_carry[BSZ*NCH*PD];

// ---- PTX helpers ----
__device__ __forceinline__ uint32_t s2u(const void* p) {
    uint32_t a;
    asm("{ .reg .u64 t; cvta.to.shared.u64 t, %1; cvt.u32.u64 %0, t; }" : "=r"(a) : "l"(p));
    return a;
}
__device__ __forceinline__ void cp16(uint32_t dst, const void* src) {
    asm volatile("cp.async.cg.shared.global [%0], [%1], 16;" :: "r"(dst), "l"(src) : "memory");
}
__device__ __forceinline__ void ldm_x4(uint32_t* r, uint32_t addr) {
    asm volatile("ldmatrix.sync.aligned.m8n8.x4.shared.b16 {%0,%1,%2,%3}, [%4];"
                 : "=r"(r[0]), "=r"(r[1]), "=r"(r[2]), "=r"(r[3]) : "r"(addr));
}
__device__ __forceinline__ void mma16816(float* d, const uint32_t* a, uint32_t b0, uint32_t b1) {
    asm volatile("mma.sync.aligned.m16n8k16.row.col.f32.f16.f16.f32 "
                 "{%0,%1,%2,%3}, {%4,%5,%6,%7}, {%8,%9}, {%0,%1,%2,%3};"
                 : "+f"(d[0]), "+f"(d[1]), "+f"(d[2]), "+f"(d[3])
                 : "r"(a[0]), "r"(a[1]), "r"(a[2]), "r"(a[3]), "r"(b0), "r"(b1));
}

// ---- prep: discretization + weight assembly ----
__global__ void prep1_kernel(const float* __restrict__ Lre,
                             const float* __restrict__ Lim,
                             const float* __restrict__ logstep) {
    int p = threadIdx.x;
    if (p >= PD) return;
    double lre = (double)Lre[p], lim = (double)Lim[p];
    double st  = exp((double)logstep[p]);
    double ar = lre * st, ai = lim * st;
    double er = exp(ar);
    double lr = er * cos(ai), li = er * sin(ai);
    g_lambda[p] = make_float2((float)lr, (float)li);
    double eS = exp(ar * (double)CH);
    g_lamS[p]  = make_float2((float)(eS * cos(ai * (double)CH)),
                             (float)(eS * sin(ai * (double)CH)));
    double nr = lr - 1.0, ni = li;
    double d2 = lre * lre + lim * lim;
    g_coef[p] = make_float2((float)((nr * lre + ni * lim) / d2),
                            (float)((ni * lre - nr * lim) / d2));
}

__global__ void prep2_kernel(const float* __restrict__ B,
                             const float* __restrict__ C) {
    int tot = HD * HD;
    for (int idx = blockIdx.x * blockDim.x + threadIdx.x;
         idx < 2 * tot; idx += gridDim.x * blockDim.x) {
        if (idx < tot) {
            int h = idx >> 9, n = idx & 511;     // W1[k=h][n]
            int p = n >> 1;
            float2 c = g_coef[p];
            float b0 = B[((size_t)p * HD + h) * 2 + 0];
            float b1 = B[((size_t)p * HD + h) * 2 + 1];
            g_W1[idx] = (n & 1) ? fmaf(c.x, b1,  c.y * b0)
                                : fmaf(c.x, b0, -c.y * b1);
        } else {
            int j = idx - tot;
            int k = j >> 9, h = j & 511;         // W2[k][n=h]
            int p = k >> 1;
            float cv = C[((size_t)h * PD + p) * 2 + (k & 1)];
            g_W2[j] = (k & 1) ? (-2.0f * cv) : (2.0f * cv);
        }
    }
}

// W[k][n] fp32 -> transposed fp16 hi [n][k]
__global__ void packw_kernel() {
    for (int idx = blockIdx.x * blockDim.x + threadIdx.x;
         idx < 2 * HD * HD; idx += gridDim.x * blockDim.x) {
        int which = idx >> 18;
        int j = idx & (HD * HD - 1);
        int n = j >> 9, k = j & 511;
        float v = which ? g_W2[k * 512 + n] : g_W1[k * 512 + n];
        (which ? g_W2h : g_W1h)[n * 512 + k] = __float2half_rn(v);
    }
}

// x fp32 -> Ah/Al fp16 row-major
__global__ void convx_kernel(const float* __restrict__ x) {
    size_t nseg = (size_t)MROWS * 64;
    for (size_t g = (size_t)blockIdx.x * blockDim.x + threadIdx.x;
         g < nseg; g += (size_t)gridDim.x * blockDim.x) {
        size_t m = g >> 6; int k8 = (int)(g & 63);
        const float4* s4 = (const float4*)(x + m * 512 + k8 * 8);
        float4 a = s4[0], b = s4[1];
        float v[8] = {a.x, a.y, a.z, a.w, b.x, b.y, b.z, b.w};
        uint32_t hi[4], lo[4];
        #pragma unroll
        for (int i = 0; i < 4; i++) {
            __half ha = __float2half_rn(v[2*i]), hb = __float2half_rn(v[2*i+1]);
            float ra = v[2*i]   - __half2float(ha);
            float rb = v[2*i+1] - __half2float(hb);
            __half2 H = __halves2half2(ha, hb);
            __half2 L = __floats2half2_rn(ra, rb);
            hi[i] = *(uint32_t*)&H; lo[i] = *(uint32_t*)&L;
        }
        size_t off = m * 512 + k8 * 8;
        *(uint4*)(g_Ah + off) = make_uint4(hi[0], hi[1], hi[2], hi[3]);
        *(uint4*)(g_Al + off) = make_uint4(lo[0], lo[1], lo[2], lo[3]);
    }
}

// ---- 3-pass chunked complex scan (pass 1 read-only) ----
__global__ void scan1_kernel() {
    int tid = blockIdx.x * 256 + threadIdx.x;
    int p = tid & (PD - 1);
    int c = (tid >> 8) & (NCH - 1);
    int b = tid >> 14;
    float2 lam = g_lambda[p];
    float xr = 0.f, xi = 0.f;
    const float2* base = (const float2*)g_Bu + ((size_t)(b * LD + c * CH)) * PD + p;
    #pragma unroll 8
    for (int j = 0; j < CH; j++) {
        float2 v = base[(size_t)j * PD];
        float nr = fmaf(lam.x, xr, fmaf(-lam.y, xi, v.x));
        float ni = fmaf(lam.y, xr, fmaf( lam.x, xi, v.y));
        xr = nr; xi = ni;
    }
    g_bout[(b * NCH + c) * PD + p] = make_float2(xr, xi);
}

__global__ void scan2_kernel() {
    int b = blockIdx.x;
    int p = threadIdx.x;
    float2 lS = g_lamS[p];
    float cr = 0.f, ci = 0.f;
    for (int c = 0; c < NCH; c++) {
        int idx = (b * NCH + c) * PD + p;
        g_carry[idx] = make_float2(cr, ci);
        float2 bo = g_bout[idx];
        float nr = fmaf(lS.x, cr, fmaf(-lS.y, ci, bo.x));
        float ni = fmaf(lS.y, cr, fmaf( lS.x, ci, bo.y));
        cr = nr; ci = ni;
    }
}

// re-run local recurrence from carry + fp16 split-convert of xs -> Ah/Al
__global__ void convxs_kernel() {
    int tid = blockIdx.x * 256 + threadIdx.x;
    int p = tid & (PD - 1);
    int c = (tid >> 8) & (NCH - 1);
    int b = tid >> 14;
    float2 lam = g_lambda[p];
    float2 car = g_carry[(b * NCH + c) * PD + p];  // state entering this chunk
    float tr = car.x, ti = car.y;
    const float2* src = (const float2*)g_Bu + ((size_t)(b * LD + c * CH)) * PD + p;
    size_t m0 = (size_t)b * LD + c * CH;
    #pragma unroll 4
    for (int j = 0; j < CH; j++) {
        float2 v = src[(size_t)j * PD];
        float nr = fmaf(lam.x, tr, fmaf(-lam.y, ti, v.x));
        float ni = fmaf(lam.y, tr, fmaf( lam.x, ti, v.y));
        tr = nr; ti = ni;
        size_t off = (m0 + j) * 512 + 2 * p;
        __half hr = __float2half_rn(tr), hm = __float2half_rn(ti);
        float rr = tr - __half2float(hr), ri = ti - __half2float(hm);
        __half2 H = __halves2half2(hr, hm);
        __half2 L = __floats2half2_rn(rr, ri);
        *(uint32_t*)(g_Ah + off) = *(uint32_t*)&H;
        *(uint32_t*)(g_Al + off) = *(uint32_t*)&L;
    }
}

// ---- HMMA fp16 split GEMM: C[128,128] per CTA, K = 2 terms x 512 ----
// MODE 0: g_Bu = x(Ah/Al) @ W1h ; MODE 1: out = xs(Ah/Al) @ W2h + D*x
#define NSTG 4
#define STGB 16384            // A 8KB + B 8KB per stage
#define GSMEM (NSTG*STGB)     // 64 KB
#define NITER 32              // 2 terms x 16 k-tiles

template <int MODE>
__global__ void __launch_bounds__(256, 2)
gemm_kernel(const float* __restrict__ skipX,
            float* __restrict__ Cext,
            const float* __restrict__ Dv) {
    extern __shared__ __align__(1024) unsigned char smem[];
    uint32_t sa = s2u(smem);
    int tid = threadIdx.x, wid = tid >> 5, lane = tid & 31;
    int row0 = blockIdx.y * 128, col0 = blockIdx.x * 128;
    float* Co = MODE ? Cext : g_Bu;
    const __half* Wh = MODE ? g_W2h : g_W1h;

    int lr = tid >> 2, lc = tid & 3;       // loader: row 0..63(x2), 16B chunk 0..3

    auto load_stage = [&](int st, int it) {
        int seg = it >> 4, kt = it & 15;
        const __half* As = seg ? g_Al : g_Ah;
        int k0 = kt * 32 + lc * 8;
        uint32_t sA = sa + st * STGB;
        uint32_t sB = sA + 8192;
        #pragma unroll
        for (int i = 0; i < 2; i++) {
            int r = lr + i * 64;
            cp16(sA + (uint32_t)(lc * 128 + r) * 16, As + (size_t)(row0 + r) * 512 + k0);
            cp16(sB + (uint32_t)(lc * 128 + r) * 16, Wh + (size_t)(col0 + r) * 512 + k0);
        }
        asm volatile("cp.async.commit_group;" ::: "memory");
    };

    float acc[2][8][4];
    #pragma unroll
    for (int i = 0; i < 2; i++)
        #pragma unroll
        for (int j = 0; j < 8; j++)
            #pragma unroll
            for (int q = 0; q < 4; q++) acc[i][j][q] = 0.f;

    load_stage(0, 0);
    load_stage(1, 1);
    load_stage(2, 2);

    int wm = (wid & 3) * 32, wn = (wid >> 2) * 64;
    int lrow = lane & 15, lhalf = lane >> 4;

    #pragma unroll 1
    for (int it = 0; it < NITER; it++) {
        int st = it & 3;
        asm volatile("cp.async.wait_group 2;" ::: "memory");
        __syncthreads();
        if (it + 3 < NITER) load_stage((it + 3) & 3, it + 3);
        else asm volatile("cp.async.commit_group;" ::: "memory");

        uint32_t sA = sa + st * STGB, sB = sA + 8192;
        #pragma unroll
        for (int s = 0; s < 2; s++) {
            int ch = s * 2 + lhalf;
            uint32_t a[2][4], b[4][4];
            #pragma unroll
            for (int tm = 0; tm < 2; tm++)
                ldm_x4(a[tm], sA + (uint32_t)(ch * 128 + wm + tm * 16 + lrow) * 16);
            #pragma unroll
            for (int tp = 0; tp < 4; tp++)
                ldm_x4(b[tp], sB + (uint32_t)(ch * 128 + wn + tp * 16 + lrow) * 16);
            #pragma unroll
            for (int tm = 0; tm < 2; tm++)
                #pragma unroll
                for (int tn = 0; tn < 8; tn++) {
                    int tp = tn >> 1, w = tn & 1;
                    mma16816(acc[tm][tn], a[tm], b[tp][w], b[tp][w + 2]);
                }
        }
    }

    // epilogue: d-frag lane mapping: rows l>>2 (+8), cols (l&3)*2 (+1)
    int rbase = row0 + wm + (lane >> 2);
    int nb0 = col0 + wn + (lane & 3) * 2;
    #pragma unroll
    for (int tm = 0; tm < 2; tm++) {
        #pragma unroll
        for (int tn = 0; tn < 8; tn++) {
            int r = rbase + tm * 16;
            int n = nb0 + tn * 8;
            float2 v0 = make_float2(acc[tm][tn][0], acc[tm][tn][1]);
            float2 v1 = make_float2(acc[tm][tn][2], acc[tm][tn][3]);
            if (MODE == 1) {
                float d0 = Dv[n], d1 = Dv[n + 1];
                float2 x0 = *(const float2*)&skipX[(size_t)r * 512 + n];
                float2 x1 = *(const float2*)&skipX[(size_t)(r + 8) * 512 + n];
                v0.x = fmaf(d0, x0.x, v0.x); v0.y = fmaf(d1, x0.y, v0.y);
                v1.x = fmaf(d0, x1.x, v1.x); v1.y = fmaf(d1, x1.y, v1.y);
            }
            *(float2*)&Co[(size_t)r * 512 + n]       = v0;
            *(float2*)&Co[(size_t)(r + 8) * 512 + n] = v1;
        }
    }
}

// ---- launch ----
extern "C" void kernel_launch(void* const* d_in, const int* in_sizes, int n_in,
                              void* d_out, int out_size) {
    const float* x       = (const float*)d_in[0];
    const float* Lre     = (const float*)d_in[1];
    const float* Lim     = (const float*)d_in[2];
    const float* B       = (const float*)d_in[3];
    const float* C       = (const float*)d_in[4];
    const float* D       = (const float*)d_in[5];
    const float* logstep = (const float*)d_in[6];
    float* out = (float*)d_out;

    static int attr_done = 0;
    if (!attr_done) {
        cudaFuncSetAttribute(gemm_kernel<0>, cudaFuncAttributeMaxDynamicSharedMemorySize, GSMEM);
        cudaFuncSetAttribute(gemm_kernel<1>, cudaFuncAttributeMaxDynamicSharedMemorySize, GSMEM);
        attr_done = 1;
    }

    prep1_kernel<<<1, 256>>>(Lre, Lim, logstep);
    prep2_kernel<<<256, 256>>>(B, C);
    packw_kernel<<<512, 256>>>();
    convx_kernel<<<2048, 256>>>(x);

    dim3 gg(4, 256);   // (N/128, M/128)
    gemm_kernel<0><<<gg, 256, GSMEM>>>(nullptr, nullptr, nullptr);

    scan1_kernel<<<(BSZ * NCH * PD) / 256, 256>>>();
    scan2_kernel<<<BSZ, PD>>>();
    convxs_kernel<<<(BSZ * NCH * PD) / 256, 256>>>();

    gemm_kernel<1><<<gg, 256, GSMEM>>>(x, out, D);
}

// round 8
// speedup vs baseline: 1.8788x; 1.1554x over previous
#include <cuda_runtime.h>
#include <cuda_fp16.h>
#include <math.h>
#include <stdint.h>

#define HD 512
#define PD 256
#define LD 4096
#define BSZ 8
#define MROWS (BSZ*LD)      // 32768
#define CH 64
#define NCH (LD/CH)         // 64

// ---- device scratch (no allocation allowed) ----
__device__ __align__(16) float g_Bu[(size_t)MROWS*HD];        // 64 MB fp32
__device__ __align__(16) __half g_Ah[(size_t)MROWS*HD];       // 32 MB [m][k]
__device__ __align__(16) __half g_W1h[HD*HD];                 // [n][k] fp16
__device__ __align__(16) __half g_W2h[HD*HD];
__device__ float2 g_lambda[PD];
__device__ float2 g_lamS[PD];
__device__ float2 g_coef[PD];
__device__ float2 g_bout [BSZ*NCH*PD];
__device__ float2 g_carry[BSZ*NCH*PD];

// ---- PTX helpers ----
__device__ __forceinline__ uint32_t s2u(const void* p) {
    uint32_t a;
    asm("{ .reg .u64 t; cvta.to.shared.u64 t, %1; cvt.u32.u64 %0, t; }" : "=r"(a) : "l"(p));
    return a;
}
__device__ __forceinline__ void cp16(uint32_t dst, const void* src) {
    asm volatile("cp.async.cg.shared.global [%0], [%1], 16;" :: "r"(dst), "l"(src) : "memory");
}
__device__ __forceinline__ void ldm_x4(uint32_t* r, uint32_t addr) {
    asm volatile("ldmatrix.sync.aligned.m8n8.x4.shared.b16 {%0,%1,%2,%3}, [%4];"
                 : "=r"(r[0]), "=r"(r[1]), "=r"(r[2]), "=r"(r[3]) : "r"(addr));
}
__device__ __forceinline__ void mma16816(float* d, const uint32_t* a, uint32_t b0, uint32_t b1) {
    asm volatile("mma.sync.aligned.m16n8k16.row.col.f32.f16.f16.f32 "
                 "{%0,%1,%2,%3}, {%4,%5,%6,%7}, {%8,%9}, {%0,%1,%2,%3};"
                 : "+f"(d[0]), "+f"(d[1]), "+f"(d[2]), "+f"(d[3])
                 : "r"(a[0]), "r"(a[1]), "r"(a[2]), "r"(a[3]), "r"(b0), "r"(b1));
}

// ---- prep: discretization ----
__global__ void prep1_kernel(const float* __restrict__ Lre,
                             const float* __restrict__ Lim,
                             const float* __restrict__ logstep) {
    int p = threadIdx.x;
    if (p >= PD) return;
    double lre = (double)Lre[p], lim = (double)Lim[p];
    double st  = exp((double)logstep[p]);
    double ar = lre * st, ai = lim * st;
    double er = exp(ar);
    double lr = er * cos(ai), li = er * sin(ai);
    g_lambda[p] = make_float2((float)lr, (float)li);
    double eS = exp(ar * (double)CH);
    g_lamS[p]  = make_float2((float)(eS * cos(ai * (double)CH)),
                             (float)(eS * sin(ai * (double)CH)));
    double nr = lr - 1.0, ni = li;
    double d2 = lre * lre + lim * lim;
    g_coef[p] = make_float2((float)((nr * lre + ni * lim) / d2),
                            (float)((ni * lre - nr * lim) / d2));
}

// weight assembly: directly write transposed fp16 [n][k]
__global__ void prep2_kernel(const float* __restrict__ B,
                             const float* __restrict__ C) {
    int tot = HD * HD;
    for (int idx = blockIdx.x * blockDim.x + threadIdx.x;
         idx < 2 * tot; idx += gridDim.x * blockDim.x) {
        if (idx < tot) {
            // W1h[n][k]: original W1[k=h][n], n=2p(+1)
            int n = idx >> 9, k = idx & 511;
            int p = n >> 1;
            float2 c = g_coef[p];
            float b0 = B[((size_t)p * HD + k) * 2 + 0];
            float b1 = B[((size_t)p * HD + k) * 2 + 1];
            float v = (n & 1) ? fmaf(c.x, b1,  c.y * b0)
                              : fmaf(c.x, b0, -c.y * b1);
            g_W1h[n * 512 + k] = __float2half_rn(v);
        } else {
            // W2h[n=h][k]: original W2[k][h], k=2p(+1)
            int j = idx - tot;
            int n = j >> 9, k = j & 511;
            int p = k >> 1;
            float cv = C[((size_t)n * PD + p) * 2 + (k & 1)];
            float v = (k & 1) ? (-2.0f * cv) : (2.0f * cv);
            g_W2h[n * 512 + k] = __float2half_rn(v);
        }
    }
}

// x fp32 -> Ah fp16 row-major
__global__ void convx_kernel(const float* __restrict__ x) {
    size_t nseg = (size_t)MROWS * 64;
    for (size_t g = (size_t)blockIdx.x * blockDim.x + threadIdx.x;
         g < nseg; g += (size_t)gridDim.x * blockDim.x) {
        size_t m = g >> 6; int k8 = (int)(g & 63);
        const float4* s4 = (const float4*)(x + m * 512 + k8 * 8);
        float4 a = s4[0], b = s4[1];
        __half2 h0 = __floats2half2_rn(a.x, a.y);
        __half2 h1 = __floats2half2_rn(a.z, a.w);
        __half2 h2 = __floats2half2_rn(b.x, b.y);
        __half2 h3 = __floats2half2_rn(b.z, b.w);
        *(uint4*)(g_Ah + m * 512 + k8 * 8) =
            make_uint4(*(uint32_t*)&h0, *(uint32_t*)&h1, *(uint32_t*)&h2, *(uint32_t*)&h3);
    }
}

// ---- chunked complex scan (pass 1 read-only) ----
__global__ void scan1_kernel() {
    int tid = blockIdx.x * 256 + threadIdx.x;
    int p = tid & (PD - 1);
    int c = (tid >> 8) & (NCH - 1);
    int b = tid >> 14;
    float2 lam = g_lambda[p];
    float xr = 0.f, xi = 0.f;
    const float2* base = (const float2*)g_Bu + ((size_t)(b * LD + c * CH)) * PD + p;
    #pragma unroll 8
    for (int j = 0; j < CH; j++) {
        float2 v = base[(size_t)j * PD];
        float nr = fmaf(lam.x, xr, fmaf(-lam.y, xi, v.x));
        float ni = fmaf(lam.y, xr, fmaf( lam.x, xi, v.y));
        xr = nr; xi = ni;
    }
    g_bout[(b * NCH + c) * PD + p] = make_float2(xr, xi);
}

__global__ void scan2_kernel() {
    int b = blockIdx.x;
    int p = threadIdx.x;
    float2 lS = g_lamS[p];
    float cr = 0.f, ci = 0.f;
    for (int c = 0; c < NCH; c++) {
        int idx = (b * NCH + c) * PD + p;
        g_carry[idx] = make_float2(cr, ci);
        float2 bo = g_bout[idx];
        float nr = fmaf(lS.x, cr, fmaf(-lS.y, ci, bo.x));
        float ni = fmaf(lS.y, cr, fmaf( lS.x, ci, bo.y));
        cr = nr; ci = ni;
    }
}

// re-run local recurrence from carry + fp16 convert of xs -> Ah
__global__ void convxs_kernel() {
    int tid = blockIdx.x * 256 + threadIdx.x;
    int p = tid & (PD - 1);
    int c = (tid >> 8) & (NCH - 1);
    int b = tid >> 14;
    float2 lam = g_lambda[p];
    float2 car = g_carry[(b * NCH + c) * PD + p];
    float tr = car.x, ti = car.y;
    const float2* src = (const float2*)g_Bu + ((size_t)(b * LD + c * CH)) * PD + p;
    size_t m0 = (size_t)b * LD + c * CH;
    #pragma unroll 4
    for (int j = 0; j < CH; j++) {
        float2 v = src[(size_t)j * PD];
        float nr = fmaf(lam.x, tr, fmaf(-lam.y, ti, v.x));
        float ni = fmaf(lam.y, tr, fmaf( lam.x, ti, v.y));
        tr = nr; ti = ni;
        __half2 H = __floats2half2_rn(tr, ti);
        *(uint32_t*)(g_Ah + (m0 + j) * 512 + 2 * p) = *(uint32_t*)&H;
    }
}

// ---- HMMA fp16 GEMM: C[128,128] per CTA, K = 512 ----
// MODE 0: g_Bu = x(Ah) @ W1h ; MODE 1: out = xs(Ah) @ W2h + D*x
#define NSTG 4
#define STGB 16384            // A 8KB + B 8KB per stage
#define GSMEM (NSTG*STGB)     // 64 KB
#define NITER 16

template <int MODE>
__global__ void __launch_bounds__(256, 2)
gemm_kernel(const float* __restrict__ skipX,
            float* __restrict__ Cext,
            const float* __restrict__ Dv) {
    extern __shared__ __align__(1024) unsigned char smem[];
    uint32_t sa = s2u(smem);
    int tid = threadIdx.x, wid = tid >> 5, lane = tid & 31;
    int row0 = blockIdx.y * 128, col0 = blockIdx.x * 128;
    float* Co = MODE ? Cext : g_Bu;
    const __half* Wh = MODE ? g_W2h : g_W1h;

    int lr = tid >> 2, lc = tid & 3;       // loader: row 0..63(x2), 16B chunk 0..3

    auto load_stage = [&](int st, int it) {
        int k0 = it * 32 + lc * 8;
        uint32_t sA = sa + st * STGB;
        uint32_t sB = sA + 8192;
        #pragma unroll
        for (int i = 0; i < 2; i++) {
            int r = lr + i * 64;
            cp16(sA + (uint32_t)(lc * 128 + r) * 16, g_Ah + (size_t)(row0 + r) * 512 + k0);
            cp16(sB + (uint32_t)(lc * 128 + r) * 16, Wh + (size_t)(col0 + r) * 512 + k0);
        }
        asm volatile("cp.async.commit_group;" ::: "memory");
    };

    float acc[2][8][4];
    #pragma unroll
    for (int i = 0; i < 2; i++)
        #pragma unroll
        for (int j = 0; j < 8; j++)
            #pragma unroll
            for (int q = 0; q < 4; q++) acc[i][j][q] = 0.f;

    load_stage(0, 0);
    load_stage(1, 1);
    load_stage(2, 2);

    int wm = (wid & 3) * 32, wn = (wid >> 2) * 64;
    int lrow = lane & 15, lhalf = lane >> 4;

    #pragma unroll 1
    for (int it = 0; it < NITER; it++) {
        int st = it & 3;
        asm volatile("cp.async.wait_group 2;" ::: "memory");
        __syncthreads();
        if (it + 3 < NITER) load_stage((it + 3) & 3, it + 3);
        else asm volatile("cp.async.commit_group;" ::: "memory");

        uint32_t sA = sa + st * STGB, sB = sA + 8192;
        #pragma unroll
        for (int s = 0; s < 2; s++) {
            int ch = s * 2 + lhalf;
            uint32_t a[2][4], b[4][4];
            #pragma unroll
            for (int tm = 0; tm < 2; tm++)
                ldm_x4(a[tm], sA + (uint32_t)(ch * 128 + wm + tm * 16 + lrow) * 16);
            #pragma unroll
            for (int tp = 0; tp < 4; tp++)
                ldm_x4(b[tp], sB + (uint32_t)(ch * 128 + wn + tp * 16 + lrow) * 16);
            #pragma unroll
            for (int tm = 0; tm < 2; tm++)
                #pragma unroll
                for (int tn = 0; tn < 8; tn++) {
                    int tp = tn >> 1, w = tn & 1;
                    mma16816(acc[tm][tn], a[tm], b[tp][w], b[tp][w + 2]);
                }
        }
    }

    // epilogue: d-frag lane mapping: rows l>>2 (+8), cols (l&3)*2 (+1)
    int rbase = row0 + wm + (lane >> 2);
    int nb0 = col0 + wn + (lane & 3) * 2;
    #pragma unroll
    for (int tm = 0; tm < 2; tm++) {
        #pragma unroll
        for (int tn = 0; tn < 8; tn++) {
            int r = rbase + tm * 16;
            int n = nb0 + tn * 8;
            float2 v0 = make_float2(acc[tm][tn][0], acc[tm][tn][1]);
            float2 v1 = make_float2(acc[tm][tn][2], acc[tm][tn][3]);
            if (MODE == 1) {
                float d0 = Dv[n], d1 = Dv[n + 1];
                float2 x0 = *(const float2*)&skipX[(size_t)r * 512 + n];
                float2 x1 = *(const float2*)&skipX[(size_t)(r + 8) * 512 + n];
                v0.x = fmaf(d0, x0.x, v0.x); v0.y = fmaf(d1, x0.y, v0.y);
                v1.x = fmaf(d0, x1.x, v1.x); v1.y = fmaf(d1, x1.y, v1.y);
            }
            *(float2*)&Co[(size_t)r * 512 + n]       = v0;
            *(float2*)&Co[(size_t)(r + 8) * 512 + n] = v1;
        }
    }
}

// ---- launch ----
extern "C" void kernel_launch(void* const* d_in, const int* in_sizes, int n_in,
                              void* d_out, int out_size) {
    const float* x       = (const float*)d_in[0];
    const float* Lre     = (const float*)d_in[1];
    const float* Lim     = (const float*)d_in[2];
    const float* B       = (const float*)d_in[3];
    const float* C       = (const float*)d_in[4];
    const float* D       = (const float*)d_in[5];
    const float* logstep = (const float*)d_in[6];
    float* out = (float*)d_out;

    static int attr_done = 0;
    if (!attr_done) {
        cudaFuncSetAttribute(gemm_kernel<0>, cudaFuncAttributeMaxDynamicSharedMemorySize, GSMEM);
        cudaFuncSetAttribute(gemm_kernel<1>, cudaFuncAttributeMaxDynamicSharedMemorySize, GSMEM);
        attr_done = 1;
    }

    prep1_kernel<<<1, 256>>>(Lre, Lim, logstep);
    prep2_kernel<<<256, 256>>>(B, C);
    convx_kernel<<<2048, 256>>>(x);

    dim3 gg(4, 256);   // (N/128, M/128)
    gemm_kernel<0><<<gg, 256, GSMEM>>>(nullptr, nullptr, nullptr);

    scan1_kernel<<<(BSZ * NCH * PD) / 256, 256>>>();
    scan2_kernel<<<BSZ, PD>>>();
    convxs_kernel<<<(BSZ * NCH * PD) / 256, 256>>>();

    gemm_kernel<1><<<gg, 256, GSMEM>>>(x, out, D);
}

// round 9
// speedup vs baseline: 2.5538x; 1.3592x over previous
#include <cuda_runtime.h>
#include <cuda_fp16.h>
#include <math.h>
#include <stdint.h>

#define HD 512
#define PD 256
#define LD 4096
#define BSZ 8
#define MROWS (BSZ*LD)      // 32768
#define CH 64
#define NCH (LD/CH)         // 64

// ---- device scratch (no allocation allowed) ----
__device__ __align__(16) float g_Bu[(size_t)MROWS*HD];        // 64 MB fp32
__device__ __align__(16) __half g_Ah[(size_t)MROWS*HD];       // 32 MB [m][k]
__device__ __align__(16) __half g_W1h[HD*HD];                 // [n][k] fp16
__device__ __align__(16) __half g_W2h[HD*HD];
__device__ float2 g_lambda[PD];
__device__ float2 g_lamS[PD];
__device__ float2 g_coef[PD];
__device__ float2 g_bout [BSZ*NCH*PD];
__device__ float2 g_carry[BSZ*NCH*PD];

// ---- PTX helpers ----
__device__ __forceinline__ uint32_t s2u(const void* p) {
    uint32_t a;
    asm("{ .reg .u64 t; cvta.to.shared.u64 t, %1; cvt.u32.u64 %0, t; }" : "=r"(a) : "l"(p));
    return a;
}
__device__ __forceinline__ void cp16(uint32_t dst, const void* src) {
    asm volatile("cp.async.cg.shared.global [%0], [%1], 16;" :: "r"(dst), "l"(src) : "memory");
}
__device__ __forceinline__ void ldm_x4(uint32_t* r, uint32_t addr) {
    asm volatile("ldmatrix.sync.aligned.m8n8.x4.shared.b16 {%0,%1,%2,%3}, [%4];"
                 : "=r"(r[0]), "=r"(r[1]), "=r"(r[2]), "=r"(r[3]) : "r"(addr));
}
__device__ __forceinline__ void mma16816(float* d, const uint32_t* a, uint32_t b0, uint32_t b1) {
    asm volatile("mma.sync.aligned.m16n8k16.row.col.f32.f16.f16.f32 "
                 "{%0,%1,%2,%3}, {%4,%5,%6,%7}, {%8,%9}, {%0,%1,%2,%3};"
                 : "+f"(d[0]), "+f"(d[1]), "+f"(d[2]), "+f"(d[3])
                 : "r"(a[0]), "r"(a[1]), "r"(a[2]), "r"(a[3]), "r"(b0), "r"(b1));
}

// ---- prep: discretization ----
__global__ void prep1_kernel(const float* __restrict__ Lre,
                             const float* __restrict__ Lim,
                             const float* __restrict__ logstep) {
    int p = threadIdx.x;
    if (p >= PD) return;
    double lre = (double)Lre[p], lim = (double)Lim[p];
    double st  = exp((double)logstep[p]);
    double ar = lre * st, ai = lim * st;
    double er = exp(ar);
    double lr = er * cos(ai), li = er * sin(ai);
    g_lambda[p] = make_float2((float)lr, (float)li);
    double eS = exp(ar * (double)CH);
    g_lamS[p]  = make_float2((float)(eS * cos(ai * (double)CH)),
                             (float)(eS * sin(ai * (double)CH)));
    double nr = lr - 1.0, ni = li;
    double d2 = lre * lre + lim * lim;
    g_coef[p] = make_float2((float)((nr * lre + ni * lim) / d2),
                            (float)((ni * lre - nr * lim) / d2));
}

// weight assembly: directly write transposed fp16 [n][k]
__global__ void prep2_kernel(const float* __restrict__ B,
                             const float* __restrict__ C) {
    int tot = HD * HD;
    for (int idx = blockIdx.x * blockDim.x + threadIdx.x;
         idx < 2 * tot; idx += gridDim.x * blockDim.x) {
        if (idx < tot) {
            int n = idx >> 9, k = idx & 511;
            int p = n >> 1;
            float2 c = g_coef[p];
            float b0 = B[((size_t)p * HD + k) * 2 + 0];
            float b1 = B[((size_t)p * HD + k) * 2 + 1];
            float v = (n & 1) ? fmaf(c.x, b1,  c.y * b0)
                              : fmaf(c.x, b0, -c.y * b1);
            g_W1h[n * 512 + k] = __float2half_rn(v);
        } else {
            int j = idx - tot;
            int n = j >> 9, k = j & 511;
            int p = k >> 1;
            float cv = C[((size_t)n * PD + p) * 2 + (k & 1)];
            float v = (k & 1) ? (-2.0f * cv) : (2.0f * cv);
            g_W2h[n * 512 + k] = __float2half_rn(v);
        }
    }
}

// x fp32 -> Ah fp16 row-major
__global__ void convx_kernel(const float* __restrict__ x) {
    size_t nseg = (size_t)MROWS * 64;
    for (size_t g = (size_t)blockIdx.x * blockDim.x + threadIdx.x;
         g < nseg; g += (size_t)gridDim.x * blockDim.x) {
        size_t m = g >> 6; int k8 = (int)(g & 63);
        const float4* s4 = (const float4*)(x + m * 512 + k8 * 8);
        float4 a = s4[0], b = s4[1];
        __half2 h0 = __floats2half2_rn(a.x, a.y);
        __half2 h1 = __floats2half2_rn(a.z, a.w);
        __half2 h2 = __floats2half2_rn(b.x, b.y);
        __half2 h3 = __floats2half2_rn(b.z, b.w);
        *(uint4*)(g_Ah + m * 512 + k8 * 8) =
            make_uint4(*(uint32_t*)&h0, *(uint32_t*)&h1, *(uint32_t*)&h2, *(uint32_t*)&h3);
    }
}

// ---- chunked complex scan (pass 1 read-only) ----
__global__ void scan1_kernel() {
    int tid = blockIdx.x * 256 + threadIdx.x;
    int p = tid & (PD - 1);
    int c = (tid >> 8) & (NCH - 1);
    int b = tid >> 14;
    float2 lam = g_lambda[p];
    float xr = 0.f, xi = 0.f;
    const float2* base = (const float2*)g_Bu + ((size_t)(b * LD + c * CH)) * PD + p;
    #pragma unroll 8
    for (int j = 0; j < CH; j++) {
        float2 v = base[(size_t)j * PD];
        float nr = fmaf(lam.x, xr, fmaf(-lam.y, xi, v.x));
        float ni = fmaf(lam.y, xr, fmaf( lam.x, xi, v.y));
        xr = nr; xi = ni;
    }
    g_bout[(b * NCH + c) * PD + p] = make_float2(xr, xi);
}

__global__ void scan2_kernel() {
    int b = blockIdx.x;
    int p = threadIdx.x;
    float2 lS = g_lamS[p];
    float cr = 0.f, ci = 0.f;
    for (int c = 0; c < NCH; c++) {
        int idx = (b * NCH + c) * PD + p;
        g_carry[idx] = make_float2(cr, ci);
        float2 bo = g_bout[idx];
        float nr = fmaf(lS.x, cr, fmaf(-lS.y, ci, bo.x));
        float ni = fmaf(lS.y, cr, fmaf( lS.x, ci, bo.y));
        cr = nr; ci = ni;
    }
}

// re-run local recurrence from carry + fp16 convert of xs -> Ah
__global__ void convxs_kernel() {
    int tid = blockIdx.x * 256 + threadIdx.x;
    int p = tid & (PD - 1);
    int c = (tid >> 8) & (NCH - 1);
    int b = tid >> 14;
    float2 lam = g_lambda[p];
    float2 car = g_carry[(b * NCH + c) * PD + p];
    float tr = car.x, ti = car.y;
    const float2* src = (const float2*)g_Bu + ((size_t)(b * LD + c * CH)) * PD + p;
    size_t m0 = (size_t)b * LD + c * CH;
    #pragma unroll 4
    for (int j = 0; j < CH; j++) {
        float2 v = src[(size_t)j * PD];
        float nr = fmaf(lam.x, tr, fmaf(-lam.y, ti, v.x));
        float ni = fmaf(lam.y, tr, fmaf( lam.x, ti, v.y));
        tr = nr; ti = ni;
        __half2 H = __floats2half2_rn(tr, ti);
        *(uint32_t*)(g_Ah + (m0 + j) * 512 + 2 * p) = *(uint32_t*)&H;
    }
}

// ---- HMMA fp16 GEMM: C[128,128] per CTA, K = 512, BK = 64 ----
// MODE 0: g_Bu = x(Ah) @ W1h ; MODE 1: out = xs(Ah) @ W2h + D*x
#define NSTG 3
#define STGB 32768            // A 16KB + B 16KB per stage
#define GSMEM (NSTG*STGB)     // 96 KB
#define NITER 8               // 512 / 64

template <int MODE>
__global__ void __launch_bounds__(256, 2)
gemm_kernel(const float* __restrict__ skipX,
            float* __restrict__ Cext,
            const float* __restrict__ Dv) {
    extern __shared__ __align__(1024) unsigned char smem[];
    uint32_t sa = s2u(smem);
    int tid = threadIdx.x, wid = tid >> 5, lane = tid & 31;
    int row0 = blockIdx.y * 128, col0 = blockIdx.x * 128;
    float* Co = MODE ? Cext : g_Bu;
    const __half* Wh = MODE ? g_W2h : g_W1h;

    // loader: 16B chunk lc (0..7), base row r (0..31), 4 row-passes
    int lc = tid & 7, lr = tid >> 3;

    auto load_stage = [&](int st, int it) {
        int k0 = it * 64 + lc * 8;
        uint32_t sA = sa + st * STGB;
        uint32_t sB = sA + 16384;
        #pragma unroll
        for (int i = 0; i < 4; i++) {
            int r = lr + i * 32;
            cp16(sA + (uint32_t)(lc * 128 + r) * 16, g_Ah + (size_t)(row0 + r) * 512 + k0);
            cp16(sB + (uint32_t)(lc * 128 + r) * 16, Wh + (size_t)(col0 + r) * 512 + k0);
        }
        asm volatile("cp.async.commit_group;" ::: "memory");
    };

    float acc[2][8][4];
    #pragma unroll
    for (int i = 0; i < 2; i++)
        #pragma unroll
        for (int j = 0; j < 8; j++)
            #pragma unroll
            for (int q = 0; q < 4; q++) acc[i][j][q] = 0.f;

    load_stage(0, 0);
    load_stage(1, 1);

    int wm = (wid & 3) * 32, wn = (wid >> 2) * 64;
    int lrow = lane & 15, lhalf = lane >> 4;

    #pragma unroll 1
    for (int it = 0; it < NITER; it++) {
        int st = it % NSTG;
        asm volatile("cp.async.wait_group 1;" ::: "memory");
        __syncthreads();
        if (it + 2 < NITER) load_stage((it + 2) % NSTG, it + 2);
        else asm volatile("cp.async.commit_group;" ::: "memory");

        uint32_t sA = sa + st * STGB, sB = sA + 16384;
        #pragma unroll
        for (int s = 0; s < 4; s++) {
            int ch = s * 2 + lhalf;
            uint32_t a[2][4], b[4][4];
            #pragma unroll
            for (int tm = 0; tm < 2; tm++)
                ldm_x4(a[tm], sA + (uint32_t)(ch * 128 + wm + tm * 16 + lrow) * 16);
            #pragma unroll
            for (int tp = 0; tp < 4; tp++)
                ldm_x4(b[tp], sB + (uint32_t)(ch * 128 + wn + tp * 16 + lrow) * 16);
            #pragma unroll
            for (int tm = 0; tm < 2; tm++)
                #pragma unroll
                for (int tn = 0; tn < 8; tn++) {
                    int tp = tn >> 1, w = tn & 1;
                    mma16816(acc[tm][tn], a[tm], b[tp][w], b[tp][w + 2]);
                }
        }
    }

    // epilogue: d-frag lane mapping: rows l>>2 (+8), cols (l&3)*2 (+1)
    int rbase = row0 + wm + (lane >> 2);
    int nb0 = col0 + wn + (lane & 3) * 2;
    #pragma unroll
    for (int tm = 0; tm < 2; tm++) {
        #pragma unroll
        for (int tn = 0; tn < 8; tn++) {
            int r = rbase + tm * 16;
            int n = nb0 + tn * 8;
            float2 v0 = make_float2(acc[tm][tn][0], acc[tm][tn][1]);
            float2 v1 = make_float2(acc[tm][tn][2], acc[tm][tn][3]);
            if (MODE == 1) {
                float d0 = Dv[n], d1 = Dv[n + 1];
                float2 x0 = *(const float2*)&skipX[(size_t)r * 512 + n];
                float2 x1 = *(const float2*)&skipX[(size_t)(r + 8) * 512 + n];
                v0.x = fmaf(d0, x0.x, v0.x); v0.y = fmaf(d1, x0.y, v0.y);
                v1.x = fmaf(d0, x1.x, v1.x); v1.y = fmaf(d1, x1.y, v1.y);
            }
            *(float2*)&Co[(size_t)r * 512 + n]       = v0;
            *(float2*)&Co[(size_t)(r + 8) * 512 + n] = v1;
        }
    }
}

// ---- launch ----
extern "C" void kernel_launch(void* const* d_in, const int* in_sizes, int n_in,
                              void* d_out, int out_size) {
    const float* x       = (const float*)d_in[0];
    const float* Lre     = (const float*)d_in[1];
    const float* Lim     = (const float*)d_in[2];
    const float* B       = (const float*)d_in[3];
    const float* C       = (const float*)d_in[4];
    const float* D       = (const float*)d_in[5];
    const float* logstep = (const float*)d_in[6];
    float* out = (float*)d_out;

    static int attr_done = 0;
    if (!attr_done) {
        cudaFuncSetAttribute(gemm_kernel<0>, cudaFuncAttributeMaxDynamicSharedMemorySize, GSMEM);
        cudaFuncSetAttribute(gemm_kernel<1>, cudaFuncAttributeMaxDynamicSharedMemorySize, GSMEM);
        attr_done = 1;
    }

    prep1_kernel<<<1, 256>>>(Lre, Lim, logstep);
    prep2_kernel<<<256, 256>>>(B, C);
    convx_kernel<<<2048, 256>>>(x);

    dim3 gg(4, 256);   // (N/128, M/128)
    gemm_kernel<0><<<gg, 256, GSMEM>>>(nullptr, nullptr, nullptr);

    scan1_kernel<<<(BSZ * NCH * PD) / 256, 256>>>();
    scan2_kernel<<<BSZ, PD>>>();
    convxs_kernel<<<(BSZ * NCH * PD) / 256, 256>>>();

    gemm_kernel<1><<<gg, 256, GSMEM>>>(x, out, D);
}